// round 1
// baseline (speedup 1.0000x reference)
#include <cuda_runtime.h>
#include <math.h>

#define BB 16
#define TT 4096
#define DM 1024
#define DP 64
#define NC 4
#define NTOK (BB*TT)            // 65536

// output layout (flat fp32, tuple order)
#define OUT_OFF    0ull
#define USTD_OFF   67108864ull
#define TEMP_OFF   67174400ull
#define ATTN_OFF   67174401ull
#define ORTHO_OFF  67436545ull
#define GEO_OFF    67436546ull
#define LATENT_OFF 67436547ull

// scratch
__device__ float g_sum[BB*DM];
__device__ float g_sumsq[BB*DM];
__device__ float g_mean[BB*DM];
__device__ float g_rs[BB*DM];
__device__ float g_Q[(size_t)NTOK*DP];
__device__ float g_H[(size_t)NTOK*DP];
__device__ float g_gate[NTOK];
__device__ float g_temp_sum;
__device__ float g_cos_sum;

__device__ __forceinline__ float wsum(float v){
#pragma unroll
    for (int m = 16; m; m >>= 1) v += __shfl_xor_sync(0xffffffffu, v, m);
    return v;
}
__device__ __forceinline__ float wmax(float v){
#pragma unroll
    for (int m = 16; m; m >>= 1) v = fmaxf(v, __shfl_xor_sync(0xffffffffu, v, m));
    return v;
}
__device__ __forceinline__ float softplusf(float v){
    return (v > 20.f) ? v : log1pf(expf(v));
}

// ---------------- init ----------------
__global__ void k_init(){
    int i = blockIdx.x*256 + threadIdx.x;
    if (i < BB*DM){ g_sum[i] = 0.f; g_sumsq[i] = 0.f; }
    if (i == 0){ g_temp_sum = 0.f; g_cos_sum = 0.f; }
}

// ---------------- stats over T (chunked) ----------------
#define SCHUNK 128
__global__ __launch_bounds__(1024) void k_stats(const float* __restrict__ x){
    int b = blockIdx.x;
    int chunk = blockIdx.y;
    int d = threadIdx.x;
    const float* p = x + ((size_t)b*TT + (size_t)chunk*SCHUNK)*DM + d;
    float s = 0.f, s2 = 0.f;
#pragma unroll 4
    for (int t = 0; t < SCHUNK; t++){
        float v = p[(size_t)t*DM];
        s += v; s2 += v*v;
    }
    atomicAdd(&g_sum[b*DM + d], s);
    atomicAdd(&g_sumsq[b*DM + d], s2);
}

__global__ void k_finstats(){
    int i = blockIdx.x*256 + threadIdx.x;
    if (i < BB*DM){
        float s = g_sum[i], s2 = g_sumsq[i];
        float mean = s / (float)TT;
        float var = (s2 - s*mean) / (float)(TT - 1);
        var = fmaxf(var, 0.f);
        float sd = sqrtf(var) + 1e-5f;
        g_mean[i] = mean;
        g_rs[i] = 1.f / sd;
    }
}

// ---------------- GEMM1: Q = x_norm @ Wp + bp   (128 tok x 64 j tile, K=1024) ----------------
__global__ __launch_bounds__(256) void k_gemm1(const float* __restrict__ x,
                                               const float* __restrict__ Wp,
                                               const float* __restrict__ bp){
    __shared__ float xs[128][33];
    __shared__ float ws[32][DP];
    __shared__ float mS[DM], rS[DM];
    int tid = threadIdx.x;
    int tok0 = blockIdx.x * 128;
    int b = tok0 >> 12;           // T=4096
    const float* mrow = g_mean + b*DM;
    const float* rrow = g_rs + b*DM;
    for (int i = tid; i < DM; i += 256){ mS[i] = mrow[i]; rS[i] = rrow[i]; }
    __syncthreads();

    float acc[8][4];
#pragma unroll
    for (int i = 0; i < 8; i++){ acc[i][0]=0.f; acc[i][1]=0.f; acc[i][2]=0.f; acc[i][3]=0.f; }
    int jg = tid & 15;   // 16 groups * 4 cols
    int tg = tid >> 4;   // 16 groups * 8 tokens

    for (int kb = 0; kb < DM; kb += 32){
#pragma unroll
        for (int p = 0; p < 4; p++){
            int i = tid + p*256;
            int r = i >> 3, c4 = (i & 7)*4;
            float4 v = *(const float4*)(x + (size_t)(tok0 + r)*DM + kb + c4);
            xs[r][c4+0] = (v.x - mS[kb+c4+0]) * rS[kb+c4+0];
            xs[r][c4+1] = (v.y - mS[kb+c4+1]) * rS[kb+c4+1];
            xs[r][c4+2] = (v.z - mS[kb+c4+2]) * rS[kb+c4+2];
            xs[r][c4+3] = (v.w - mS[kb+c4+3]) * rS[kb+c4+3];
        }
#pragma unroll
        for (int p = 0; p < 2; p++){
            int i = tid + p*256;
            int r = i >> 4, c4 = (i & 15)*4;
            *(float4*)&ws[r][c4] = *(const float4*)(Wp + (size_t)(kb + r)*DP + c4);
        }
        __syncthreads();
#pragma unroll
        for (int kk = 0; kk < 32; kk++){
            float4 bv = *(const float4*)&ws[kk][jg*4];
#pragma unroll
            for (int i2 = 0; i2 < 8; i2++){
                float a = xs[tg*8 + i2][kk];
                acc[i2][0] += a*bv.x; acc[i2][1] += a*bv.y;
                acc[i2][2] += a*bv.z; acc[i2][3] += a*bv.w;
            }
        }
        __syncthreads();
    }
    float4 bpv = *(const float4*)(bp + jg*4);
#pragma unroll
    for (int i2 = 0; i2 < 8; i2++){
        float4 o;
        o.x = acc[i2][0] + bpv.x; o.y = acc[i2][1] + bpv.y;
        o.z = acc[i2][2] + bpv.z; o.w = acc[i2][3] + bpv.w;
        *(float4*)(g_Q + (size_t)(tok0 + tg*8 + i2)*DP + jg*4) = o;
    }
}

// ---------------- per-token kernel (warp per token, 8 tokens/warp) ----------------
#define TPW 8
__global__ __launch_bounds__(256) void k_token(const float* __restrict__ cent,
                                               const float* __restrict__ ln_g,
                                               const float* __restrict__ ln_b,
                                               const float* __restrict__ W1,
                                               const float* __restrict__ b1,
                                               const float* __restrict__ W2,
                                               const float* __restrict__ b2,
                                               const float* __restrict__ s_logits,
                                               const float* __restrict__ s_evid,
                                               const float* __restrict__ s_thr,
                                               const float* __restrict__ s_slope,
                                               float* __restrict__ dout){
    __shared__ float W1s[DP*DP], W2s[DP*DP];
    __shared__ float cents[NC][DP], Kns[NC][DP];
    __shared__ float lngS[DP], lnbS[DP], b1s[DP], b2s[DP];
    __shared__ float qns[8][DP], hss[8][DP];
    int tid = threadIdx.x, lane = tid & 31, wid = tid >> 5;

    for (int i = tid; i < DP*DP; i += 256){ W1s[i] = W1[i]; W2s[i] = W2[i]; }
    if (tid < DP){ lngS[tid]=ln_g[tid]; lnbS[tid]=ln_b[tid]; b1s[tid]=b1[tid]; b2s[tid]=b2[tid]; }
    if (tid < NC*DP) cents[tid >> 6][tid & 63] = cent[tid];
    __syncthreads();
    if (wid < NC){
        float c0 = cents[wid][lane], c1 = cents[wid][lane+32];
        float ss = wsum(c0*c0 + c1*c1);
        float inv = 1.f / fmaxf(sqrtf(ss), 1e-12f);
        Kns[wid][lane] = c0*inv; Kns[wid][lane+32] = c1*inv;
    }
    __syncthreads();

    float spl = softplusf(s_logits[0]);
    float spe = softplusf(s_evid[0]);
    float thr = s_thr[0], slope = s_slope[0];

    float taccum = 0.f, caccum = 0.f;
    int wg = blockIdx.x*8 + wid;

    for (int it = 0; it < TPW; it++){
        int t = wg*TPW + it;
        const float* q = g_Q + (size_t)t*DP;
        float q0 = q[lane], q1 = q[lane+32];
        float mu = wsum(q0 + q1) * (1.f/64.f);
        float d0 = q0 - mu, d1 = q1 - mu;
        float var = wsum(d0*d0 + d1*d1) * (1.f/64.f);
        float rstd = rsqrtf(var + 1e-5f);
        float y0 = d0*rstd*lngS[lane] + lnbS[lane];
        float y1 = d1*rstd*lngS[lane+32] + lnbS[lane+32];
        float n2 = wsum(y0*y0 + y1*y1);
        float nrm = sqrtf(n2);
        float inv = 1.f / fmaxf(nrm, 1e-12f);
        float qn0 = y0*inv, qn1 = y1*inv;
        qns[wid][lane] = qn0; qns[wid][lane+32] = qn1;

        float sim[NC];
#pragma unroll
        for (int n = 0; n < NC; n++)
            sim[n] = wsum(qn0*Kns[n][lane] + qn1*Kns[n][lane+32]);
        float athr = 0.25f*(sim[0]+sim[1]+sim[2]+sim[3]);
        float ev[NC], mx = -1e30f, S = 0.f;
#pragma unroll
        for (int n = 0; n < NC; n++){
            ev[n] = softplusf((sim[n] - athr)*5.0f) * spe;
            S += ev[n];
            mx = fmaxf(mx, ev[n]);
        }
        S += (float)NC;
        float ustd = (float)NC / S;
        float uresp = 1.f / (1.f + log1pf(mx * (float)NC));
        float Temp = 0.1f + 0.9f / (1.f + expf(-slope*(uresp - thr)));
        float lg[NC], lm = -1e30f;
#pragma unroll
        for (int n = 0; n < NC; n++){ lg[n] = sim[n]*spl/Temp; lm = fmaxf(lm, lg[n]); }
        float es = 0.f, e[NC];
#pragma unroll
        for (int n = 0; n < NC; n++){ e[n] = expf(lg[n]-lm); es += e[n]; }
        float attn[NC];
#pragma unroll
        for (int n = 0; n < NC; n++) attn[n] = e[n]/es;

        float hg0 = 0.f, hg1 = 0.f;
#pragma unroll
        for (int n = 0; n < NC; n++){
            hg0 += attn[n]*cents[n][lane];
            hg1 += attn[n]*cents[n][lane+32];
        }
        __syncwarp();
        float h0 = b1s[lane], h1 = b1s[lane+32];
#pragma unroll
        for (int d = 0; d < DP; d++){
            float qd = qns[wid][d];
            h0 += qd*W1s[d*DP + lane];
            h1 += qd*W1s[d*DP + lane + 32];
        }
        h0 = tanhf(h0); h1 = tanhf(h1);
        hss[wid][lane] = h0; hss[wid][lane+32] = h1;
        __syncwarp();
        float o0 = b2s[lane], o1 = b2s[lane+32];
#pragma unroll
        for (int j = 0; j < DP; j++){
            float hj = hss[wid][j];
            o0 += hj*W2s[j*DP + lane];
            o1 += hj*W2s[j*DP + lane + 32];
        }
        float hr0 = hg0 + o0, hr1 = hg1 + o1;
        g_H[(size_t)t*DP + lane] = hr0;
        g_H[(size_t)t*DP + lane + 32] = hr1;

        float dot = wsum(hr0*y0 + hr1*y1);
        float hn2 = wsum(hr0*hr0 + hr1*hr1);
        float cosv = dot / (fmaxf(sqrtf(hn2), 1e-8f) * fmaxf(nrm, 1e-8f));
        if (lane == 0){
            taccum += Temp;
            caccum += cosv;
            dout[USTD_OFF + (size_t)t] = ustd;
            dout[ATTN_OFF + (size_t)t*4 + 0] = attn[0];
            dout[ATTN_OFF + (size_t)t*4 + 1] = attn[1];
            dout[ATTN_OFF + (size_t)t*4 + 2] = attn[2];
            dout[ATTN_OFF + (size_t)t*4 + 3] = attn[3];
            float ig = (1.f - uresp);
            g_gate[t] = ig*ig;
        }
        __syncwarp();
    }
    if (lane == 0){
        atomicAdd(&g_temp_sum, taccum);
        atomicAdd(&g_cos_sum, caccum);
    }
}

// ---------------- GEMM2: out = gate*(H@Wo + bo) + x   (64 tok x 128 col tile, K=64) ----------------
__global__ __launch_bounds__(256) void k_gemm2(const float* __restrict__ x,
                                               const float* __restrict__ Wo,
                                               const float* __restrict__ bo,
                                               float* __restrict__ out){
    __shared__ float hsm[DP][68];     // transposed: [k][tok]
    __shared__ float wos[DP][128];
    __shared__ float gs[64];
    int tid = threadIdx.x;
    int tok0 = blockIdx.y * 64;
    int db = blockIdx.x * 128;
#pragma unroll
    for (int p = 0; p < 4; p++){
        int i = tid + p*256;
        int r = i & 63, cg = i >> 6;   // cg 0..15
        float4 v = *(const float4*)(g_H + (size_t)(tok0 + r)*DP + cg*4);
        hsm[cg*4+0][r] = v.x; hsm[cg*4+1][r] = v.y;
        hsm[cg*4+2][r] = v.z; hsm[cg*4+3][r] = v.w;
    }
#pragma unroll
    for (int p = 0; p < 8; p++){
        int i = tid + p*256;
        int r = i >> 5, c4 = (i & 31)*4;
        *(float4*)&wos[r][c4] = *(const float4*)(Wo + (size_t)r*DM + db + c4);
    }
    if (tid < 64) gs[tid] = g_gate[tok0 + tid];
    __syncthreads();

    float acc[8][4];
#pragma unroll
    for (int i = 0; i < 8; i++){ acc[i][0]=0.f; acc[i][1]=0.f; acc[i][2]=0.f; acc[i][3]=0.f; }
    int jg = tid & 31;   // 32 groups * 4 cols
    int tg = tid >> 5;   // 8 groups * 8 tokens
#pragma unroll
    for (int kk = 0; kk < DP; kk++){
        float4 bv = *(const float4*)&wos[kk][jg*4];
        float4 a0 = *(const float4*)&hsm[kk][tg*8];
        float4 a1 = *(const float4*)&hsm[kk][tg*8 + 4];
        acc[0][0] += a0.x*bv.x; acc[0][1] += a0.x*bv.y; acc[0][2] += a0.x*bv.z; acc[0][3] += a0.x*bv.w;
        acc[1][0] += a0.y*bv.x; acc[1][1] += a0.y*bv.y; acc[1][2] += a0.y*bv.z; acc[1][3] += a0.y*bv.w;
        acc[2][0] += a0.z*bv.x; acc[2][1] += a0.z*bv.y; acc[2][2] += a0.z*bv.z; acc[2][3] += a0.z*bv.w;
        acc[3][0] += a0.w*bv.x; acc[3][1] += a0.w*bv.y; acc[3][2] += a0.w*bv.z; acc[3][3] += a0.w*bv.w;
        acc[4][0] += a1.x*bv.x; acc[4][1] += a1.x*bv.y; acc[4][2] += a1.x*bv.z; acc[4][3] += a1.x*bv.w;
        acc[5][0] += a1.y*bv.x; acc[5][1] += a1.y*bv.y; acc[5][2] += a1.y*bv.z; acc[5][3] += a1.y*bv.w;
        acc[6][0] += a1.z*bv.x; acc[6][1] += a1.z*bv.y; acc[6][2] += a1.z*bv.z; acc[6][3] += a1.z*bv.w;
        acc[7][0] += a1.w*bv.x; acc[7][1] += a1.w*bv.y; acc[7][2] += a1.w*bv.z; acc[7][3] += a1.w*bv.w;
    }
    float4 bov = *(const float4*)(bo + db + jg*4);
#pragma unroll
    for (int i2 = 0; i2 < 8; i2++){
        int t = tok0 + tg*8 + i2;
        float g = gs[tg*8 + i2];
        size_t off = (size_t)t*DM + db + jg*4;
        float4 xv = *(const float4*)(x + off);
        float4 o;
        o.x = g*(acc[i2][0] + bov.x) + xv.x;
        o.y = g*(acc[i2][1] + bov.y) + xv.y;
        o.z = g*(acc[i2][2] + bov.z) + xv.z;
        o.w = g*(acc[i2][3] + bov.w) + xv.w;
        *(float4*)(out + off) = o;
    }
}

// ---------------- scalars: ortho, temp mean, latent, geo ----------------
__global__ void k_final(const float* __restrict__ cent, float* __restrict__ dout){
    __shared__ float Kn[NC][DP];
    __shared__ float norms[NC];
    __shared__ float part[16];
    int tid = threadIdx.x;   // 64 threads
    if (tid < NC){
        float ss = 0.f;
        for (int d = 0; d < DP; d++){ float c = cent[tid*DP + d]; ss += c*c; }
        norms[tid] = fmaxf(sqrtf(ss), 1e-12f);
    }
    __syncthreads();
    if (tid < DP){
        for (int n = 0; n < NC; n++) Kn[n][tid] = cent[n*DP + tid] / norms[n];
    }
    __syncthreads();
    if (tid < 16){
        int i = tid >> 2, j = tid & 3;
        float dot = 0.f;
        for (int d = 0; d < DP; d++) dot += Kn[i][d]*Kn[j][d];
        float e2 = dot - (i == j ? 1.f : 0.f);
        part[tid] = e2*e2;
    }
    __syncthreads();
    if (tid == 0){
        float s = 0.f;
        for (int p = 0; p < 16; p++) s += part[p];
        dout[ORTHO_OFF] = s / 16.f;
        dout[TEMP_OFF] = g_temp_sum / (float)NTOK;
        dout[GEO_OFF] = 0.f;
        dout[LATENT_OFF] = 1.f - g_cos_sum / (float)NTOK;
    }
}

extern "C" void kernel_launch(void* const* d_in, const int* in_sizes, int n_in,
                              void* d_out, int out_size){
    const float* x    = (const float*)d_in[0];
    const float* Wp   = (const float*)d_in[1];
    const float* bp   = (const float*)d_in[2];
    const float* ln_g = (const float*)d_in[3];
    const float* ln_b = (const float*)d_in[4];
    const float* cent = (const float*)d_in[5];
    const float* Wo   = (const float*)d_in[6];
    const float* bo   = (const float*)d_in[7];
    const float* W1   = (const float*)d_in[8];
    const float* b1   = (const float*)d_in[9];
    const float* W2   = (const float*)d_in[10];
    const float* b2   = (const float*)d_in[11];
    const float* sl   = (const float*)d_in[12];
    const float* se   = (const float*)d_in[13];
    const float* tt   = (const float*)d_in[14];
    const float* ts   = (const float*)d_in[15];
    float* out = (float*)d_out;

    k_init<<<64, 256>>>();
    k_stats<<<dim3(BB, TT/SCHUNK), 1024>>>(x);
    k_finstats<<<64, 256>>>();
    k_gemm1<<<NTOK/128, 256>>>(x, Wp, bp);
    k_token<<<NTOK/(8*TPW), 256>>>(cent, ln_g, ln_b, W1, b1, W2, b2, sl, se, tt, ts, out);
    k_gemm2<<<dim3(DM/128, NTOK/64), 256>>>(x, Wo, bo, out);
    k_final<<<1, 64>>>(cent, out);
}